// round 15
// baseline (speedup 1.0000x reference)
#include <cuda_runtime.h>
#include <cuda_fp16.h>
#include <math.h>
#include <stdint.h>

#define BATCH 4
#define SEQ   2048
#define DIM   1024
#define NH    16
#define HD    64
#define MROWS (BATCH*SEQ)
#define ASZ   ((size_t)MROWS*2048)

// ---------------------------------------------------------------------------
// Scratch (__device__ globals; allocation-free rule)
// ---------------------------------------------------------------------------
__device__ __half g_A3[3*ASZ];
__device__ __half g_B2[(size_t)3*DIM*DIM];
__device__ __half g_B2o[(size_t)DIM*DIM];
// attention planes: Q fp16 (single), K/V fp16 hi/lo
__device__ __half g_Qh[BATCH*NH*SEQ*HD];
__device__ __half g_Kh[BATCH*NH*SEQ*HD];
__device__ __half g_Kl[BATCH*NH*SEQ*HD];
__device__ __half g_Vh[BATCH*NH*SEQ*HD];
__device__ __half g_Vl[BATCH*NH*SEQ*HD];
// RoPE tables
__device__ float g_costab[SEQ*32];
__device__ float g_sintab[SEQ*32];

__device__ __forceinline__ uint32_t smem_u32(const void* p) {
    uint32_t a;
    asm("{ .reg .u64 t; cvta.to.shared.u64 t, %1; cvt.u32.u64 %0, t; }" : "=r"(a) : "l"(p));
    return a;
}

#define LDMATRIX_X4(r0, r1, r2, r3, addr) \
    asm volatile("ldmatrix.sync.aligned.m8n8.x4.shared.b16 {%0,%1,%2,%3}, [%4];" \
        : "=r"(r0), "=r"(r1), "=r"(r2), "=r"(r3) : "r"(addr))

#define LDMATRIX_X4T(r0, r1, r2, r3, addr) \
    asm volatile("ldmatrix.sync.aligned.m8n8.x4.trans.shared.b16 {%0,%1,%2,%3}, [%4];" \
        : "=r"(r0), "=r"(r1), "=r"(r2), "=r"(r3) : "r"(addr))

#define MMA_F16(c, a, b0v, b1v) \
    asm volatile("mma.sync.aligned.m16n8k16.row.col.f32.f16.f16.f32 " \
        "{%0,%1,%2,%3}, {%4,%5,%6,%7}, {%8,%9}, {%0,%1,%2,%3};" \
        : "+f"((c)[0]), "+f"((c)[1]), "+f"((c)[2]), "+f"((c)[3]) \
        : "r"((a)[0]), "r"((a)[1]), "r"((a)[2]), "r"((a)[3]), "r"(b0v), "r"(b1v))

#define CP_ASYNC16(dst, src) \
    asm volatile("cp.async.cg.shared.global [%0], [%1], 16;" :: "r"(dst), "l"(src))
#define CP_COMMIT() asm volatile("cp.async.commit_group;" ::: "memory")
#define CP_WAIT0()  asm volatile("cp.async.wait_group 0;" ::: "memory")
#define CP_WAIT1()  asm volatile("cp.async.wait_group 1;" ::: "memory")

__device__ __forceinline__ uint32_t h2u(__half2 h) { return *reinterpret_cast<uint32_t*>(&h); }
__device__ __forceinline__ float ex2f(float x) {
    float y; asm("ex2.approx.f32 %0, %1;" : "=f"(y) : "f"(x)); return y;
}

struct h4 { __half2 a, b; };

#define QSCALE 0.18033688011112042f   // 0.125 * log2(e)

// ---------------------------------------------------------------------------
// RoPE table init
// ---------------------------------------------------------------------------
__global__ void init_tbl()
{
    int idx = blockIdx.x * blockDim.x + threadIdx.x;
    if (idx >= SEQ * 32) return;
    int lane = idx & 31;
    int s    = idx >> 5;
    float invf = (float)pow(10000.0, -(double)lane / 32.0);
    float sn, cs;
    sincosf((float)s * invf, &sn, &cs);
    g_costab[idx] = cs;
    g_sintab[idx] = sn;
}

// ---------------------------------------------------------------------------
// X split x3: f32 -> fp16 hi/lo into g_A3[z]
// ---------------------------------------------------------------------------
__global__ void split_x3(const float* __restrict__ q, const float* __restrict__ k,
                         const float* __restrict__ v)
{
    int z = blockIdx.z;
    const float* src = (z == 0) ? q : (z == 1) ? k : v;
    int i = blockIdx.x * blockDim.x + threadIdx.x;
    if (i >= MROWS * 256) return;
    int r = i >> 8, c4 = i & 255;
    float4 vv = ((const float4*)src)[i];
    __half2 h01 = __floats2half2_rn(vv.x, vv.y);
    __half2 h23 = __floats2half2_rn(vv.z, vv.w);
    __half2 l01 = __floats2half2_rn(vv.x - __half2float(__low2half(h01)),
                                    vv.y - __half2float(__high2half(h01)));
    __half2 l23 = __floats2half2_rn(vv.z - __half2float(__low2half(h23)),
                                    vv.w - __half2float(__high2half(h23)));
    __half* out = g_A3 + (size_t)z * ASZ;
    size_t base = (size_t)r * 2048 + c4 * 4;
    h4 hv; hv.a = h01; hv.b = h23;
    h4 lv; lv.a = l01; lv.b = l23;
    *(h4*)(out + base)        = hv;
    *(h4*)(out + base + 1024) = lv;
}

// ---------------------------------------------------------------------------
// W converts
// ---------------------------------------------------------------------------
__global__ void split_w3(const float* __restrict__ wq, const float* __restrict__ wk,
                         const float* __restrict__ wv)
{
    int z = blockIdx.z;
    const float* src = (z == 0) ? wq : (z == 1) ? wk : wv;
    int i = blockIdx.x * blockDim.x + threadIdx.x;
    if (i >= DIM * 256) return;
    float4 v = ((const float4*)src)[i];
    h4 hv;
    hv.a = __floats2half2_rn(v.x, v.y);
    hv.b = __floats2half2_rn(v.z, v.w);
    *(h4*)(g_B2 + (size_t)z * DIM * DIM + (size_t)i * 4) = hv;
}

__global__ void split_wo(const float* __restrict__ in)
{
    int i = blockIdx.x * blockDim.x + threadIdx.x;
    if (i >= DIM * 256) return;
    float4 v = ((const float4*)in)[i];
    h4 hv;
    hv.a = __floats2half2_rn(v.x, v.y);
    hv.b = __floats2half2_rn(v.z, v.w);
    *(h4*)(g_B2o + (size_t)i * 4) = hv;
}

// ---------------------------------------------------------------------------
// mma.sync fp16x2 GEMM, 3-stage pipeline, fused-QKV, RoPE epilogue.
// z==0 (Q): fp16 single-plane output (no lo split).
// ---------------------------------------------------------------------------
#define NST      32
#define STAGE_B  (128*144)
#define GEMM_SMEM (6*STAGE_B)            // 110592
#define EPF      136

__global__ __launch_bounds__(256)
void gemm_mma(const float* __restrict__ b0, const float* __restrict__ b1,
              const float* __restrict__ b2, float* __restrict__ dst_param,
              int opro)
{
    extern __shared__ __align__(16) char sm[];
    uint32_t sb = smem_u32(sm);

    int z = blockIdx.z;
    const float* bias = opro ? b0 : (z == 0) ? b0 : (z == 1) ? b1 : b2;
    const __half* Amat = g_A3 + (opro ? 0 : (size_t)z * ASZ);
    const __half* Bmat = opro ? g_B2o : g_B2 + (size_t)z * DIM * DIM;

    int tid  = threadIdx.x;
    int lane = tid & 31;
    int wid  = tid >> 5;
    int wm   = wid & 1;
    int wn   = wid >> 1;
    int m0 = blockIdx.y << 7, n0 = blockIdx.x << 7;

    int lr = ((lane >> 3) & 1) * 8 + (lane & 7);
    int lk = (lane >> 4) * 8;

    float c[4][4][4];
    #pragma unroll
    for (int mf = 0; mf < 4; mf++)
        #pragma unroll
        for (int nf = 0; nf < 4; nf++)
            #pragma unroll
            for (int v = 0; v < 4; v++) c[mf][nf][v] = 0.0f;

    auto load_stage = [&](int t, int buf) {
        int kp = t << 6;
        int bc = kp & 1023;
        const __half* Ab = Amat + (size_t)m0 * 2048 + kp;
        const __half* Bb = Bmat + (size_t)n0 * 1024 + bc;
        uint32_t sa  = sb + buf * STAGE_B;
        uint32_t sbb = sb + 3 * STAGE_B + buf * STAGE_B;
        #pragma unroll
        for (int it = 0; it < 4; it++) {
            int id = tid + (it << 8);
            int r = id >> 3, ch = id & 7;
            CP_ASYNC16(sa  + r * 144 + (ch << 4), Ab + (size_t)r * 2048 + (ch << 3));
            CP_ASYNC16(sbb + r * 144 + (ch << 4), Bb + (size_t)r * 1024 + (ch << 3));
        }
        CP_COMMIT();
    };

    load_stage(0, 0);
    load_stage(1, 1);

    #pragma unroll 1
    for (int t = 0; t < NST; t++) {
        if (t + 1 < NST) { CP_WAIT1(); } else { CP_WAIT0(); }
        __syncthreads();
        if (t + 2 < NST) load_stage(t + 2, (t + 2) % 3);

        int buf = t % 3;
        uint32_t sa  = sb + buf * STAGE_B;
        uint32_t sbb = sb + 3 * STAGE_B + buf * STAGE_B;

        #pragma unroll
        for (int kk = 0; kk < 64; kk += 16) {
            uint32_t a[4][4];
            #pragma unroll
            for (int mf = 0; mf < 4; mf++) {
                uint32_t ad = sa + (uint32_t)(wm * 64 + mf * 16 + lr) * 144 + (kk + lk) * 2;
                LDMATRIX_X4(a[mf][0], a[mf][1], a[mf][2], a[mf][3], ad);
            }
            uint32_t b[2][4];
            #pragma unroll
            for (int nb = 0; nb < 2; nb++) {
                uint32_t bd = sbb + (uint32_t)(wn * 32 + nb * 16 + lr) * 144 + (kk + lk) * 2;
                LDMATRIX_X4(b[nb][0], b[nb][1], b[nb][2], b[nb][3], bd);
            }
            #pragma unroll
            for (int mf = 0; mf < 4; mf++) {
                #pragma unroll
                for (int nf = 0; nf < 4; nf++) {
                    int nb = nf >> 1;
                    uint32_t bb0 = (nf & 1) ? b[nb][1] : b[nb][0];
                    uint32_t bb1 = (nf & 1) ? b[nb][3] : b[nb][2];
                    MMA_F16(c[mf][nf], a[mf], bb0, bb1);
                }
            }
        }
        __syncthreads();
    }

    int rq = lane >> 2, cq = (lane & 3) * 2;
    float2 bv[4];
    #pragma unroll
    for (int nf = 0; nf < 4; nf++) {
        int col = n0 + wn * 32 + nf * 8 + cq;
        bv[nf] = make_float2(bias[col], bias[col + 1]);
    }

    if (opro) {
        #pragma unroll
        for (int mf = 0; mf < 4; mf++) {
            #pragma unroll
            for (int nf = 0; nf < 4; nf++) {
                int r   = m0 + wm * 64 + mf * 16 + rq;
                int col = n0 + wn * 32 + nf * 8 + cq;
                float2 lo = make_float2(c[mf][nf][0] + bv[nf].x, c[mf][nf][1] + bv[nf].y);
                float2 hi = make_float2(c[mf][nf][2] + bv[nf].x, c[mf][nf][3] + bv[nf].y);
                *(float2*)(dst_param + (size_t)r * 1024 + col)       = lo;
                *(float2*)(dst_param + (size_t)(r + 8) * 1024 + col) = hi;
            }
        }
        return;
    }

    // ---- fused RoPE + fp16 epilogue (z=0: Q single plane; z=1/2: hi/lo) ----
    float* st = (float*)sm;
    #pragma unroll
    for (int mf = 0; mf < 4; mf++) {
        #pragma unroll
        for (int nf = 0; nf < 4; nf++) {
            int r   = wm * 64 + mf * 16 + rq;
            int col = wn * 32 + nf * 8 + cq;
            *(float2*)&st[r * EPF + col] =
                make_float2(c[mf][nf][0] + bv[nf].x, c[mf][nf][1] + bv[nf].y);
            *(float2*)&st[(r + 8) * EPF + col] =
                make_float2(c[mf][nf][2] + bv[nf].x, c[mf][nf][3] + bv[nf].y);
        }
    }
    __syncthreads();

    int row = tid >> 1;
    int hsel = tid & 1;
    int m = m0 + row;
    int b = m >> 11, s = m & 2047;
    int h = (n0 >> 6) + hsel;

    float x[64];
    const float* xr = st + row * EPF + hsel * 64;
    int rot = row & 15;
    #pragma unroll
    for (int i = 0; i < 16; i++) {
        int ii = (i + rot) & 15;
        *(float4*)&x[ii * 4] = *(const float4*)&xr[ii * 4];
    }

    __half* dh = (z == 0) ? g_Qh : (z == 1) ? g_Kh : g_Vh;
    __half* dl = (z == 1) ? g_Kl : g_Vl;     // unused for z==0
    size_t off = ((size_t)(b * NH + h) * SEQ + s) << 6;

    #pragma unroll
    for (int g = 0; g < 4; g++) {
        float v0[8], v1[8];
        if (z < 2) {
            #pragma unroll
            for (int j = 0; j < 8; j++) {
                int d = g * 8 + j;
                float cs = g_costab[(s << 5) + d];
                float sn = g_sintab[(s << 5) + d];
                v0[j] = x[d]      * cs - x[2*d + 1] * sn;
                v1[j] = x[d + 32] * cs + x[2*d]     * sn;
                if (z == 0) { v0[j] *= QSCALE; v1[j] *= QSCALE; }
            }
        } else {
            #pragma unroll
            for (int j = 0; j < 8; j++) {
                int d = g * 8 + j;
                v0[j] = x[d];
                v1[j] = x[d + 32];
            }
        }
        uint4 h0v, h1v;
        uint32_t* h0p = (uint32_t*)&h0v;
        uint32_t* h1p = (uint32_t*)&h1v;
        if (z == 0) {
            #pragma unroll
            for (int p = 0; p < 4; p++) {
                h0p[p] = h2u(__floats2half2_rn(v0[2*p], v0[2*p+1]));
                h1p[p] = h2u(__floats2half2_rn(v1[2*p], v1[2*p+1]));
            }
            *(uint4*)(dh + off + g * 8)      = h0v;
            *(uint4*)(dh + off + 32 + g * 8) = h1v;
        } else {
            uint4 l0v, l1v;
            uint32_t* l0p = (uint32_t*)&l0v;
            uint32_t* l1p = (uint32_t*)&l1v;
            #pragma unroll
            for (int p = 0; p < 4; p++) {
                __half2 hh0 = __floats2half2_rn(v0[2*p], v0[2*p+1]);
                __half2 ll0 = __floats2half2_rn(v0[2*p]   - __half2float(__low2half(hh0)),
                                                v0[2*p+1] - __half2float(__high2half(hh0)));
                h0p[p] = h2u(hh0); l0p[p] = h2u(ll0);
                __half2 hh1 = __floats2half2_rn(v1[2*p], v1[2*p+1]);
                __half2 ll1 = __floats2half2_rn(v1[2*p]   - __half2float(__low2half(hh1)),
                                                v1[2*p+1] - __half2float(__high2half(hh1)));
                h1p[p] = h2u(hh1); l1p[p] = h2u(ll1);
            }
            *(uint4*)(dh + off + g * 8)      = h0v;
            *(uint4*)(dh + off + 32 + g * 8) = h1v;
            *(uint4*)(dl + off + g * 8)      = l0v;
            *(uint4*)(dl + off + 32 + g * 8) = l1v;
        }
    }
}

// ---------------------------------------------------------------------------
// Flash attention: BM=128 (8 warps), BN=64, Q fp16 single plane in SMEM,
// K/V hi/lo double-buffered, f32 ex2 softmax, ones-MMA sums.
// S = q·kh + q·kl (Q-lo term dropped; error budget analysis in commit msg).
// SMEM: Q 18432 | KV stage0 36864 | KV stage1 36864 = 92160.
// ---------------------------------------------------------------------------
#define ROWB 144
#define QSM  18432
#define PLANE (64*ROWB)
#define KVST (4*PLANE)
#define ATTN_SMEM (QSM + 2*KVST)   // 92160

__global__ __launch_bounds__(256, 2)
void attn_mma()
{
    extern __shared__ __align__(16) char smb[];
    uint32_t sb = smem_u32(smb);

    int tid  = threadIdx.x;
    int lane = tid & 31;
    int wid  = tid >> 5;
    int bh   = blockIdx.y;
    int bx   = gridDim.x - 1 - blockIdx.x;
    int q0   = bx << 7;
    int nt   = 2 * bx + 2;

    const __half* Kh = g_Kh + (size_t)bh * SEQ * HD;
    const __half* Kl = g_Kl + (size_t)bh * SEQ * HD;
    const __half* Vh = g_Vh + (size_t)bh * SEQ * HD;
    const __half* Vl = g_Vl + (size_t)bh * SEQ * HD;

    int lr = ((lane >> 3) & 1) * 8 + (lane & 7);
    int lk = (lane >> 4) * 8;
    int rq = lane >> 2, cq = (lane & 3) * 2;

    auto load_kv = [&](int t, int stage) {
        int k0 = t << 6;
        uint32_t base = sb + QSM + stage * KVST;
        #pragma unroll
        for (int it = 0; it < 2; it++) {
            int id = tid + (it << 8);
            int r = id >> 3, ch = id & 7;
            uint32_t o = r * ROWB + (ch << 4);
            int go = ((k0 + r) << 6) + (ch << 3);
            CP_ASYNC16(base + o,             Kh + go);
            CP_ASYNC16(base + PLANE + o,     Kl + go);
            CP_ASYNC16(base + 2*PLANE + o,   Vh + go);
            CP_ASYNC16(base + 3*PLANE + o,   Vl + go);
        }
        CP_COMMIT();
    };

    // prologue: Q fp16 single plane
    {
        const __half* Qh = g_Qh + (size_t)bh * SEQ * HD;
        #pragma unroll
        for (int it = 0; it < 4; it++) {
            int id = tid + (it << 8);          // 0..1023
            int r = id >> 3, ch = id & 7;
            CP_ASYNC16(sb + r * ROWB + (ch << 4), Qh + ((q0 + r) << 6) + (ch << 3));
        }
        CP_COMMIT();
    }
    load_kv(0, 0);

    float acc[8][4];
    #pragma unroll
    for (int nf = 0; nf < 8; nf++)
        #pragma unroll
        for (int v = 0; v < 4; v++) acc[nf][v] = 0.0f;
    float lacc[4] = {0.0f, 0.0f, 0.0f, 0.0f};
    float m_i[2] = {-1e30f, -1e30f};

    int wminrow = q0 + wid*16;

    CP_WAIT0();
    __syncthreads();

    #pragma unroll 1
    for (int t = 0; t < nt; t++) {
        int k0 = t << 6;
        if (t + 1 < nt) { load_kv(t + 1, (t + 1) & 1); CP_WAIT1(); }
        __syncthreads();

        uint32_t khb = sb + QSM + (t & 1) * KVST;
        uint32_t klb = khb + PLANE;
        uint32_t vhb = khb + 2*PLANE;
        uint32_t vlb = khb + 3*PLANE;

        // ---- S = q·kh + q·kl ----
        float sc[8][4];
        #pragma unroll
        for (int nf = 0; nf < 8; nf++)
            #pragma unroll
            for (int v = 0; v < 4; v++) sc[nf][v] = 0.0f;

        #pragma unroll
        for (int kc = 0; kc < 4; kc++) {
            uint32_t qoff = (uint32_t)(wid*16 + lr) * ROWB + (kc*16 + lk) * 2;
            uint32_t qh[4];
            LDMATRIX_X4(qh[0], qh[1], qh[2], qh[3], sb + qoff);
            #pragma unroll
            for (int nb = 0; nb < 4; nb++) {
                uint32_t off = (uint32_t)(nb*16 + lr) * ROWB + (kc*16 + lk) * 2;
                uint32_t bh0, bh1, bh2, bh3, bl0, bl1, bl2, bl3;
                LDMATRIX_X4(bh0, bh1, bh2, bh3, khb + off);
                LDMATRIX_X4(bl0, bl1, bl2, bl3, klb + off);
                MMA_F16(sc[2*nb],   qh, bh0, bh2);
                MMA_F16(sc[2*nb],   qh, bl0, bl2);
                MMA_F16(sc[2*nb+1], qh, bh1, bh3);
                MMA_F16(sc[2*nb+1], qh, bl1, bl3);
            }
        }

        if (k0 + 63 > wminrow) {
            int row0 = wminrow + rq;
            #pragma unroll
            for (int nf = 0; nf < 8; nf++) {
                int col = k0 + nf*8 + cq;
                if (col     > row0)     sc[nf][0] = -1e30f;
                if (col + 1 > row0)     sc[nf][1] = -1e30f;
                if (col     > row0 + 8) sc[nf][2] = -1e30f;
                if (col + 1 > row0 + 8) sc[nf][3] = -1e30f;
            }
        }

        uint32_t pr[8][2];
        #pragma unroll
        for (int i = 0; i < 2; i++) {
            float mx = -1e30f;
            #pragma unroll
            for (int nf = 0; nf < 8; nf++)
                mx = fmaxf(mx, fmaxf(sc[nf][2*i], sc[nf][2*i+1]));
            mx = fmaxf(mx, __shfl_xor_sync(0xffffffffu, mx, 1));
            mx = fmaxf(mx, __shfl_xor_sync(0xffffffffu, mx, 2));
            float mnew  = fmaxf(m_i[i], mx);
            float scale = ex2f(m_i[i] - mnew);
            float neg   = -mnew;
            #pragma unroll
            for (int nf = 0; nf < 8; nf++) {
                float p0 = ex2f(sc[nf][2*i]   + neg);
                float p1 = ex2f(sc[nf][2*i+1] + neg);
                asm("cvt.rn.f16x2.f32 %0, %1, %2;" : "=r"(pr[nf][i]) : "f"(p1), "f"(p0));
            }
            m_i[i] = mnew;
            lacc[2*i]   *= scale;
            lacc[2*i+1] *= scale;
            #pragma unroll
            for (int nf = 0; nf < 8; nf++) {
                acc[nf][2*i]   *= scale;
                acc[nf][2*i+1] *= scale;
            }
        }

        #pragma unroll
        for (int kc = 0; kc < 4; kc++) {
            uint32_t ph[4] = { pr[2*kc][0], pr[2*kc][1], pr[2*kc+1][0], pr[2*kc+1][1] };
            MMA_F16(lacc, ph, 0x3C003C00u, 0x3C003C00u);
            #pragma unroll
            for (int db = 0; db < 4; db++) {
                uint32_t off = (uint32_t)(kc*16 + (lane & 15)) * ROWB
                             + (db*16 + ((lane >> 4) << 3)) * 2;
                uint32_t vh0, vh1, vh2, vh3, vl0, vl1, vl2, vl3;
                LDMATRIX_X4T(vh0, vh1, vh2, vh3, vhb + off);
                LDMATRIX_X4T(vl0, vl1, vl2, vl3, vlb + off);
                MMA_F16(acc[2*db],   ph, vh0, vh1);
                MMA_F16(acc[2*db],   ph, vl0, vl1);
                MMA_F16(acc[2*db+1], ph, vh2, vh3);
                MMA_F16(acc[2*db+1], ph, vl2, vl3);
            }
        }
        __syncthreads();
    }

    // epilogue: normalize + fp16 hi/lo split into g_A3[0]
    int b = bh >> 4, h = bh & 15;
    #pragma unroll
    for (int i = 0; i < 2; i++) {
        float inv = 1.0f / lacc[2*i];
        int s = q0 + wid*16 + rq + 8*i;
        __half* rowp = g_A3 + ((size_t)(b * SEQ + s) << 11) + (h << 6);
        #pragma unroll
        for (int nf = 0; nf < 8; nf++) {
            float v0 = acc[nf][2*i]   * inv;
            float v1 = acc[nf][2*i+1] * inv;
            __half2 hv = __floats2half2_rn(v0, v1);
            __half2 lv = __floats2half2_rn(v0 - __half2float(__low2half(hv)),
                                           v1 - __half2float(__high2half(hv)));
            *(__half2*)(rowp + nf*8 + cq)        = hv;
            *(__half2*)(rowp + 1024 + nf*8 + cq) = lv;
        }
    }
}

// ---------------------------------------------------------------------------
extern "C" void kernel_launch(void* const* d_in, const int* in_sizes, int n_in,
                              void* d_out, int out_size)
{
    const float* query = (const float*)d_in[0];
    const float* key   = (const float*)d_in[1];
    const float* value = (const float*)d_in[2];
    const float* w_q = (const float*)d_in[4];
    const float* b_q = (const float*)d_in[5];
    const float* w_k = (const float*)d_in[6];
    const float* b_k = (const float*)d_in[7];
    const float* w_v = (const float*)d_in[8];
    const float* b_v = (const float*)d_in[9];
    const float* w_o = (const float*)d_in[10];
    const float* b_o = (const float*)d_in[11];
    float* out = (float*)d_out;

    static int attr_set = 0;
    if (!attr_set) {
        cudaFuncSetAttribute(gemm_mma, cudaFuncAttributeMaxDynamicSharedMemorySize, GEMM_SMEM);
        cudaFuncSetAttribute(attn_mma, cudaFuncAttributeMaxDynamicSharedMemorySize, ATTN_SMEM);
        attr_set = 1;
    }

    init_tbl<<<SEQ*32/256, 256>>>();                             // 0
    split_x3<<<dim3(MROWS, 1, 3), 256>>>(query, key, value);     // 1
    split_w3<<<dim3(DIM, 1, 3), 256>>>(w_q, w_k, w_v);           // 2
    gemm_mma<<<dim3(DIM/128, MROWS/128, 3), 256, GEMM_SMEM>>>(b_q, b_k, b_v, nullptr, 0); // 3
    split_wo<<<DIM, 256>>>(w_o);                                 // 4
    attn_mma<<<dim3(SEQ/128, BATCH*NH), 256, ATTN_SMEM>>>();     // 5
    gemm_mma<<<dim3(DIM/128, MROWS/128, 1), 256, GEMM_SMEM>>>(b_o, nullptr, nullptr, out, 1); // 6
}

// round 16
// speedup vs baseline: 1.0728x; 1.0728x over previous
#include <cuda_runtime.h>
#include <cuda_fp16.h>
#include <math.h>
#include <stdint.h>

#define BATCH 4
#define SEQ   2048
#define DIM   1024
#define NH    16
#define HD    64
#define MROWS (BATCH*SEQ)
#define ASZ   ((size_t)MROWS*2048)

// ---------------------------------------------------------------------------
// Scratch (__device__ globals; allocation-free rule)
// ---------------------------------------------------------------------------
__device__ __half g_A3[3*ASZ];
__device__ __half g_B2[(size_t)3*DIM*DIM];
__device__ __half g_B2o[(size_t)DIM*DIM];
// attention planes: Q fp16 (single), K/V fp16 hi/lo
__device__ __half g_Qh[BATCH*NH*SEQ*HD];
__device__ __half g_Kh[BATCH*NH*SEQ*HD];
__device__ __half g_Kl[BATCH*NH*SEQ*HD];
__device__ __half g_Vh[BATCH*NH*SEQ*HD];
__device__ __half g_Vl[BATCH*NH*SEQ*HD];
// RoPE tables
__device__ float g_costab[SEQ*32];
__device__ float g_sintab[SEQ*32];

__device__ __forceinline__ uint32_t smem_u32(const void* p) {
    uint32_t a;
    asm("{ .reg .u64 t; cvta.to.shared.u64 t, %1; cvt.u32.u64 %0, t; }" : "=r"(a) : "l"(p));
    return a;
}

#define LDMATRIX_X4(r0, r1, r2, r3, addr) \
    asm volatile("ldmatrix.sync.aligned.m8n8.x4.shared.b16 {%0,%1,%2,%3}, [%4];" \
        : "=r"(r0), "=r"(r1), "=r"(r2), "=r"(r3) : "r"(addr))

#define LDMATRIX_X4T(r0, r1, r2, r3, addr) \
    asm volatile("ldmatrix.sync.aligned.m8n8.x4.trans.shared.b16 {%0,%1,%2,%3}, [%4];" \
        : "=r"(r0), "=r"(r1), "=r"(r2), "=r"(r3) : "r"(addr))

#define MMA_F16(c, a, b0v, b1v) \
    asm volatile("mma.sync.aligned.m16n8k16.row.col.f32.f16.f16.f32 " \
        "{%0,%1,%2,%3}, {%4,%5,%6,%7}, {%8,%9}, {%0,%1,%2,%3};" \
        : "+f"((c)[0]), "+f"((c)[1]), "+f"((c)[2]), "+f"((c)[3]) \
        : "r"((a)[0]), "r"((a)[1]), "r"((a)[2]), "r"((a)[3]), "r"(b0v), "r"(b1v))

#define CP_ASYNC16(dst, src) \
    asm volatile("cp.async.cg.shared.global [%0], [%1], 16;" :: "r"(dst), "l"(src))
#define CP_COMMIT() asm volatile("cp.async.commit_group;" ::: "memory")
#define CP_WAIT0()  asm volatile("cp.async.wait_group 0;" ::: "memory")
#define CP_WAIT1()  asm volatile("cp.async.wait_group 1;" ::: "memory")

__device__ __forceinline__ uint32_t h2u(__half2 h) { return *reinterpret_cast<uint32_t*>(&h); }
__device__ __forceinline__ float ex2f(float x) {
    float y; asm("ex2.approx.f32 %0, %1;" : "=f"(y) : "f"(x)); return y;
}

struct h4 { __half2 a, b; };

#define QSCALE 0.18033688011112042f   // 0.125 * log2(e)

// ---------------------------------------------------------------------------
// RoPE table init
// ---------------------------------------------------------------------------
__global__ void init_tbl()
{
    int idx = blockIdx.x * blockDim.x + threadIdx.x;
    if (idx >= SEQ * 32) return;
    int lane = idx & 31;
    int s    = idx >> 5;
    float invf = (float)pow(10000.0, -(double)lane / 32.0);
    float sn, cs;
    sincosf((float)s * invf, &sn, &cs);
    g_costab[idx] = cs;
    g_sintab[idx] = sn;
}

// ---------------------------------------------------------------------------
// X split x3: f32 -> fp16 hi/lo into g_A3[z]
// ---------------------------------------------------------------------------
__global__ void split_x3(const float* __restrict__ q, const float* __restrict__ k,
                         const float* __restrict__ v)
{
    int z = blockIdx.z;
    const float* src = (z == 0) ? q : (z == 1) ? k : v;
    int i = blockIdx.x * blockDim.x + threadIdx.x;
    if (i >= MROWS * 256) return;
    int r = i >> 8, c4 = i & 255;
    float4 vv = ((const float4*)src)[i];
    __half2 h01 = __floats2half2_rn(vv.x, vv.y);
    __half2 h23 = __floats2half2_rn(vv.z, vv.w);
    __half2 l01 = __floats2half2_rn(vv.x - __half2float(__low2half(h01)),
                                    vv.y - __half2float(__high2half(h01)));
    __half2 l23 = __floats2half2_rn(vv.z - __half2float(__low2half(h23)),
                                    vv.w - __half2float(__high2half(h23)));
    __half* out = g_A3 + (size_t)z * ASZ;
    size_t base = (size_t)r * 2048 + c4 * 4;
    h4 hv; hv.a = h01; hv.b = h23;
    h4 lv; lv.a = l01; lv.b = l23;
    *(h4*)(out + base)        = hv;
    *(h4*)(out + base + 1024) = lv;
}

// ---------------------------------------------------------------------------
// W converts
// ---------------------------------------------------------------------------
__global__ void split_w3(const float* __restrict__ wq, const float* __restrict__ wk,
                         const float* __restrict__ wv)
{
    int z = blockIdx.z;
    const float* src = (z == 0) ? wq : (z == 1) ? wk : wv;
    int i = blockIdx.x * blockDim.x + threadIdx.x;
    if (i >= DIM * 256) return;
    float4 v = ((const float4*)src)[i];
    h4 hv;
    hv.a = __floats2half2_rn(v.x, v.y);
    hv.b = __floats2half2_rn(v.z, v.w);
    *(h4*)(g_B2 + (size_t)z * DIM * DIM + (size_t)i * 4) = hv;
}

__global__ void split_wo(const float* __restrict__ in)
{
    int i = blockIdx.x * blockDim.x + threadIdx.x;
    if (i >= DIM * 256) return;
    float4 v = ((const float4*)in)[i];
    h4 hv;
    hv.a = __floats2half2_rn(v.x, v.y);
    hv.b = __floats2half2_rn(v.z, v.w);
    *(h4*)(g_B2o + (size_t)i * 4) = hv;
}

// ---------------------------------------------------------------------------
// mma.sync fp16x2 GEMM, 3-stage pipeline, fused-QKV, RoPE epilogue.
// z==0 (Q): fp16 single-plane output (no lo split).
// ---------------------------------------------------------------------------
#define NST      32
#define STAGE_B  (128*144)
#define GEMM_SMEM (6*STAGE_B)            // 110592
#define EPF      136

__global__ __launch_bounds__(256)
void gemm_mma(const float* __restrict__ b0, const float* __restrict__ b1,
              const float* __restrict__ b2, float* __restrict__ dst_param,
              int opro)
{
    extern __shared__ __align__(16) char sm[];
    uint32_t sb = smem_u32(sm);

    int z = blockIdx.z;
    const float* bias = opro ? b0 : (z == 0) ? b0 : (z == 1) ? b1 : b2;
    const __half* Amat = g_A3 + (opro ? 0 : (size_t)z * ASZ);
    const __half* Bmat = opro ? g_B2o : g_B2 + (size_t)z * DIM * DIM;

    int tid  = threadIdx.x;
    int lane = tid & 31;
    int wid  = tid >> 5;
    int wm   = wid & 1;
    int wn   = wid >> 1;
    int m0 = blockIdx.y << 7, n0 = blockIdx.x << 7;

    int lr = ((lane >> 3) & 1) * 8 + (lane & 7);
    int lk = (lane >> 4) * 8;

    float c[4][4][4];
    #pragma unroll
    for (int mf = 0; mf < 4; mf++)
        #pragma unroll
        for (int nf = 0; nf < 4; nf++)
            #pragma unroll
            for (int v = 0; v < 4; v++) c[mf][nf][v] = 0.0f;

    auto load_stage = [&](int t, int buf) {
        int kp = t << 6;
        int bc = kp & 1023;
        const __half* Ab = Amat + (size_t)m0 * 2048 + kp;
        const __half* Bb = Bmat + (size_t)n0 * 1024 + bc;
        uint32_t sa  = sb + buf * STAGE_B;
        uint32_t sbb = sb + 3 * STAGE_B + buf * STAGE_B;
        #pragma unroll
        for (int it = 0; it < 4; it++) {
            int id = tid + (it << 8);
            int r = id >> 3, ch = id & 7;
            CP_ASYNC16(sa  + r * 144 + (ch << 4), Ab + (size_t)r * 2048 + (ch << 3));
            CP_ASYNC16(sbb + r * 144 + (ch << 4), Bb + (size_t)r * 1024 + (ch << 3));
        }
        CP_COMMIT();
    };

    load_stage(0, 0);
    load_stage(1, 1);

    #pragma unroll 1
    for (int t = 0; t < NST; t++) {
        if (t + 1 < NST) { CP_WAIT1(); } else { CP_WAIT0(); }
        __syncthreads();
        if (t + 2 < NST) load_stage(t + 2, (t + 2) % 3);

        int buf = t % 3;
        uint32_t sa  = sb + buf * STAGE_B;
        uint32_t sbb = sb + 3 * STAGE_B + buf * STAGE_B;

        #pragma unroll
        for (int kk = 0; kk < 64; kk += 16) {
            uint32_t a[4][4];
            #pragma unroll
            for (int mf = 0; mf < 4; mf++) {
                uint32_t ad = sa + (uint32_t)(wm * 64 + mf * 16 + lr) * 144 + (kk + lk) * 2;
                LDMATRIX_X4(a[mf][0], a[mf][1], a[mf][2], a[mf][3], ad);
            }
            uint32_t b[2][4];
            #pragma unroll
            for (int nb = 0; nb < 2; nb++) {
                uint32_t bd = sbb + (uint32_t)(wn * 32 + nb * 16 + lr) * 144 + (kk + lk) * 2;
                LDMATRIX_X4(b[nb][0], b[nb][1], b[nb][2], b[nb][3], bd);
            }
            #pragma unroll
            for (int mf = 0; mf < 4; mf++) {
                #pragma unroll
                for (int nf = 0; nf < 4; nf++) {
                    int nb = nf >> 1;
                    uint32_t bb0 = (nf & 1) ? b[nb][1] : b[nb][0];
                    uint32_t bb1 = (nf & 1) ? b[nb][3] : b[nb][2];
                    MMA_F16(c[mf][nf], a[mf], bb0, bb1);
                }
            }
        }
        __syncthreads();
    }

    int rq = lane >> 2, cq = (lane & 3) * 2;
    float2 bv[4];
    #pragma unroll
    for (int nf = 0; nf < 4; nf++) {
        int col = n0 + wn * 32 + nf * 8 + cq;
        bv[nf] = make_float2(bias[col], bias[col + 1]);
    }

    if (opro) {
        #pragma unroll
        for (int mf = 0; mf < 4; mf++) {
            #pragma unroll
            for (int nf = 0; nf < 4; nf++) {
                int r   = m0 + wm * 64 + mf * 16 + rq;
                int col = n0 + wn * 32 + nf * 8 + cq;
                float2 lo = make_float2(c[mf][nf][0] + bv[nf].x, c[mf][nf][1] + bv[nf].y);
                float2 hi = make_float2(c[mf][nf][2] + bv[nf].x, c[mf][nf][3] + bv[nf].y);
                *(float2*)(dst_param + (size_t)r * 1024 + col)       = lo;
                *(float2*)(dst_param + (size_t)(r + 8) * 1024 + col) = hi;
            }
        }
        return;
    }

    // ---- fused RoPE + fp16 epilogue (z=0: Q single plane; z=1/2: hi/lo) ----
    float* st = (float*)sm;
    #pragma unroll
    for (int mf = 0; mf < 4; mf++) {
        #pragma unroll
        for (int nf = 0; nf < 4; nf++) {
            int r   = wm * 64 + mf * 16 + rq;
            int col = wn * 32 + nf * 8 + cq;
            *(float2*)&st[r * EPF + col] =
                make_float2(c[mf][nf][0] + bv[nf].x, c[mf][nf][1] + bv[nf].y);
            *(float2*)&st[(r + 8) * EPF + col] =
                make_float2(c[mf][nf][2] + bv[nf].x, c[mf][nf][3] + bv[nf].y);
        }
    }
    __syncthreads();

    int row = tid >> 1;
    int hsel = tid & 1;
    int m = m0 + row;
    int b = m >> 11, s = m & 2047;
    int h = (n0 >> 6) + hsel;

    float x[64];
    const float* xr = st + row * EPF + hsel * 64;
    #pragma unroll
    for (int i = 0; i < 16; i++)
        *(float4*)&x[i * 4] = *(const float4*)&xr[i * 4];

    __half* dh = (z == 0) ? g_Qh : (z == 1) ? g_Kh : g_Vh;
    __half* dl = (z == 1) ? g_Kl : g_Vl;     // unused for z==0
    size_t off = ((size_t)(b * NH + h) * SEQ + s) << 6;

    #pragma unroll
    for (int g = 0; g < 4; g++) {
        float v0[8], v1[8];
        if (z < 2) {
            #pragma unroll
            for (int j = 0; j < 8; j++) {
                int d = g * 8 + j;
                float cs = g_costab[(s << 5) + d];
                float sn = g_sintab[(s << 5) + d];
                v0[j] = x[d]      * cs - x[2*d + 1] * sn;
                v1[j] = x[d + 32] * cs + x[2*d]     * sn;
                if (z == 0) { v0[j] *= QSCALE; v1[j] *= QSCALE; }
            }
        } else {
            #pragma unroll
            for (int j = 0; j < 8; j++) {
                int d = g * 8 + j;
                v0[j] = x[d];
                v1[j] = x[d + 32];
            }
        }
        uint4 h0v, h1v;
        uint32_t* h0p = (uint32_t*)&h0v;
        uint32_t* h1p = (uint32_t*)&h1v;
        if (z == 0) {
            #pragma unroll
            for (int p = 0; p < 4; p++) {
                h0p[p] = h2u(__floats2half2_rn(v0[2*p], v0[2*p+1]));
                h1p[p] = h2u(__floats2half2_rn(v1[2*p], v1[2*p+1]));
            }
            *(uint4*)(dh + off + g * 8)      = h0v;
            *(uint4*)(dh + off + 32 + g * 8) = h1v;
        } else {
            uint4 l0v, l1v;
            uint32_t* l0p = (uint32_t*)&l0v;
            uint32_t* l1p = (uint32_t*)&l1v;
            #pragma unroll
            for (int p = 0; p < 4; p++) {
                __half2 hh0 = __floats2half2_rn(v0[2*p], v0[2*p+1]);
                __half2 ll0 = __floats2half2_rn(v0[2*p]   - __half2float(__low2half(hh0)),
                                                v0[2*p+1] - __half2float(__high2half(hh0)));
                h0p[p] = h2u(hh0); l0p[p] = h2u(ll0);
                __half2 hh1 = __floats2half2_rn(v1[2*p], v1[2*p+1]);
                __half2 ll1 = __floats2half2_rn(v1[2*p]   - __half2float(__low2half(hh1)),
                                                v1[2*p+1] - __half2float(__high2half(hh1)));
                h1p[p] = h2u(hh1); l1p[p] = h2u(ll1);
            }
            *(uint4*)(dh + off + g * 8)      = h0v;
            *(uint4*)(dh + off + 32 + g * 8) = h1v;
            *(uint4*)(dl + off + g * 8)      = l0v;
            *(uint4*)(dl + off + 32 + g * 8) = l1v;
        }
    }
}

// ---------------------------------------------------------------------------
// Flash attention: BM=128 (8 warps), BN=64, Q fp16 single plane in SMEM,
// K/V hi/lo double-buffered, f32 ex2 softmax, ones-MMA sums.
// S = q·kh + q·kl. SMEM: Q 18432 | KV stage0 36864 | KV stage1 36864 = 92160.
// ---------------------------------------------------------------------------
#define ROWB 144
#define QSM  18432
#define PLANE (64*ROWB)
#define KVST (4*PLANE)
#define ATTN_SMEM (QSM + 2*KVST)   // 92160

__global__ __launch_bounds__(256, 2)
void attn_mma()
{
    extern __shared__ __align__(16) char smb[];
    uint32_t sb = smem_u32(smb);

    int tid  = threadIdx.x;
    int lane = tid & 31;
    int wid  = tid >> 5;
    int bh   = blockIdx.y;
    int bx   = gridDim.x - 1 - blockIdx.x;
    int q0   = bx << 7;
    int nt   = 2 * bx + 2;

    const __half* Kh = g_Kh + (size_t)bh * SEQ * HD;
    const __half* Kl = g_Kl + (size_t)bh * SEQ * HD;
    const __half* Vh = g_Vh + (size_t)bh * SEQ * HD;
    const __half* Vl = g_Vl + (size_t)bh * SEQ * HD;

    int lr = ((lane >> 3) & 1) * 8 + (lane & 7);
    int lk = (lane >> 4) * 8;
    int rq = lane >> 2, cq = (lane & 3) * 2;

    auto load_kv = [&](int t, int stage) {
        int k0 = t << 6;
        uint32_t base = sb + QSM + stage * KVST;
        #pragma unroll
        for (int it = 0; it < 2; it++) {
            int id = tid + (it << 8);
            int r = id >> 3, ch = id & 7;
            uint32_t o = r * ROWB + (ch << 4);
            int go = ((k0 + r) << 6) + (ch << 3);
            CP_ASYNC16(base + o,             Kh + go);
            CP_ASYNC16(base + PLANE + o,     Kl + go);
            CP_ASYNC16(base + 2*PLANE + o,   Vh + go);
            CP_ASYNC16(base + 3*PLANE + o,   Vl + go);
        }
        CP_COMMIT();
    };

    // prologue: Q fp16 single plane
    {
        const __half* Qh = g_Qh + (size_t)bh * SEQ * HD;
        #pragma unroll
        for (int it = 0; it < 4; it++) {
            int id = tid + (it << 8);
            int r = id >> 3, ch = id & 7;
            CP_ASYNC16(sb + r * ROWB + (ch << 4), Qh + ((q0 + r) << 6) + (ch << 3));
        }
        CP_COMMIT();
    }
    load_kv(0, 0);

    float acc[8][4];
    #pragma unroll
    for (int nf = 0; nf < 8; nf++)
        #pragma unroll
        for (int v = 0; v < 4; v++) acc[nf][v] = 0.0f;
    float lacc[4] = {0.0f, 0.0f, 0.0f, 0.0f};
    float m_i[2] = {-1e30f, -1e30f};

    int wminrow = q0 + wid*16;

    CP_WAIT0();
    __syncthreads();

    #pragma unroll 1
    for (int t = 0; t < nt; t++) {
        int k0 = t << 6;
        if (t + 1 < nt) { load_kv(t + 1, (t + 1) & 1); CP_WAIT1(); }
        __syncthreads();

        uint32_t khb = sb + QSM + (t & 1) * KVST;
        uint32_t klb = khb + PLANE;
        uint32_t vhb = khb + 2*PLANE;
        uint32_t vlb = khb + 3*PLANE;

        // ---- S = q·kh + q·kl ----
        float sc[8][4];
        #pragma unroll
        for (int nf = 0; nf < 8; nf++)
            #pragma unroll
            for (int v = 0; v < 4; v++) sc[nf][v] = 0.0f;

        #pragma unroll
        for (int kc = 0; kc < 4; kc++) {
            uint32_t qoff = (uint32_t)(wid*16 + lr) * ROWB + (kc*16 + lk) * 2;
            uint32_t qh[4];
            LDMATRIX_X4(qh[0], qh[1], qh[2], qh[3], sb + qoff);
            #pragma unroll
            for (int nb = 0; nb < 4; nb++) {
                uint32_t off = (uint32_t)(nb*16 + lr) * ROWB + (kc*16 + lk) * 2;
                uint32_t bh0, bh1, bh2, bh3, bl0, bl1, bl2, bl3;
                LDMATRIX_X4(bh0, bh1, bh2, bh3, khb + off);
                LDMATRIX_X4(bl0, bl1, bl2, bl3, klb + off);
                MMA_F16(sc[2*nb],   qh, bh0, bh2);
                MMA_F16(sc[2*nb],   qh, bl0, bl2);
                MMA_F16(sc[2*nb+1], qh, bh1, bh3);
                MMA_F16(sc[2*nb+1], qh, bl1, bl3);
            }
        }

        if (k0 + 63 > wminrow) {
            int row0 = wminrow + rq;
            #pragma unroll
            for (int nf = 0; nf < 8; nf++) {
                int col = k0 + nf*8 + cq;
                if (col     > row0)     sc[nf][0] = -1e30f;
                if (col + 1 > row0)     sc[nf][1] = -1e30f;
                if (col     > row0 + 8) sc[nf][2] = -1e30f;
                if (col + 1 > row0 + 8) sc[nf][3] = -1e30f;
            }
        }

        uint32_t pr[8][2];
        #pragma unroll
        for (int i = 0; i < 2; i++) {
            float mx = -1e30f;
            #pragma unroll
            for (int nf = 0; nf < 8; nf++)
                mx = fmaxf(mx, fmaxf(sc[nf][2*i], sc[nf][2*i+1]));
            mx = fmaxf(mx, __shfl_xor_sync(0xffffffffu, mx, 1));
            mx = fmaxf(mx, __shfl_xor_sync(0xffffffffu, mx, 2));
            float mnew  = fmaxf(m_i[i], mx);
            float scale = ex2f(m_i[i] - mnew);
            float neg   = -mnew;
            #pragma unroll
            for (int nf = 0; nf < 8; nf++) {
                float p0 = ex2f(sc[nf][2*i]   + neg);
                float p1 = ex2f(sc[nf][2*i+1] + neg);
                asm("cvt.rn.f16x2.f32 %0, %1, %2;" : "=r"(pr[nf][i]) : "f"(p1), "f"(p0));
            }
            m_i[i] = mnew;
            lacc[2*i]   *= scale;
            lacc[2*i+1] *= scale;
            #pragma unroll
            for (int nf = 0; nf < 8; nf++) {
                acc[nf][2*i]   *= scale;
                acc[nf][2*i+1] *= scale;
            }
        }

        #pragma unroll
        for (int kc = 0; kc < 4; kc++) {
            uint32_t ph[4] = { pr[2*kc][0], pr[2*kc][1], pr[2*kc+1][0], pr[2*kc+1][1] };
            MMA_F16(lacc, ph, 0x3C003C00u, 0x3C003C00u);
            #pragma unroll
            for (int db = 0; db < 4; db++) {
                uint32_t off = (uint32_t)(kc*16 + (lane & 15)) * ROWB
                             + (db*16 + ((lane >> 4) << 3)) * 2;
                uint32_t vh0, vh1, vh2, vh3, vl0, vl1, vl2, vl3;
                LDMATRIX_X4T(vh0, vh1, vh2, vh3, vhb + off);
                LDMATRIX_X4T(vl0, vl1, vl2, vl3, vlb + off);
                MMA_F16(acc[2*db],   ph, vh0, vh1);
                MMA_F16(acc[2*db],   ph, vl0, vl1);
                MMA_F16(acc[2*db+1], ph, vh2, vh3);
                MMA_F16(acc[2*db+1], ph, vl2, vl3);
            }
        }
        __syncthreads();
    }

    // epilogue: normalize + fp16 hi/lo split into g_A3[0]
    int b = bh >> 4, h = bh & 15;
    #pragma unroll
    for (int i = 0; i < 2; i++) {
        float inv = 1.0f / lacc[2*i];
        int s = q0 + wid*16 + rq + 8*i;
        __half* rowp = g_A3 + ((size_t)(b * SEQ + s) << 11) + (h << 6);
        #pragma unroll
        for (int nf = 0; nf < 8; nf++) {
            float v0 = acc[nf][2*i]   * inv;
            float v1 = acc[nf][2*i+1] * inv;
            __half2 hv = __floats2half2_rn(v0, v1);
            __half2 lv = __floats2half2_rn(v0 - __half2float(__low2half(hv)),
                                           v1 - __half2float(__high2half(hv)));
            *(__half2*)(rowp + nf*8 + cq)        = hv;
            *(__half2*)(rowp + 1024 + nf*8 + cq) = lv;
        }
    }
}

// ---------------------------------------------------------------------------
extern "C" void kernel_launch(void* const* d_in, const int* in_sizes, int n_in,
                              void* d_out, int out_size)
{
    const float* query = (const float*)d_in[0];
    const float* key   = (const float*)d_in[1];
    const float* value = (const float*)d_in[2];
    const float* w_q = (const float*)d_in[4];
    const float* b_q = (const float*)d_in[5];
    const float* w_k = (const float*)d_in[6];
    const float* b_k = (const float*)d_in[7];
    const float* w_v = (const float*)d_in[8];
    const float* b_v = (const float*)d_in[9];
    const float* w_o = (const float*)d_in[10];
    const float* b_o = (const float*)d_in[11];
    float* out = (float*)d_out;

    static int attr_set = 0;
    if (!attr_set) {
        cudaFuncSetAttribute(gemm_mma, cudaFuncAttributeMaxDynamicSharedMemorySize, GEMM_SMEM);
        cudaFuncSetAttribute(attn_mma, cudaFuncAttributeMaxDynamicSharedMemorySize, ATTN_SMEM);
        attr_set = 1;
    }

    init_tbl<<<SEQ*32/256, 256>>>();                             // 0
    split_x3<<<dim3(MROWS, 1, 3), 256>>>(query, key, value);     // 1
    split_w3<<<dim3(DIM, 1, 3), 256>>>(w_q, w_k, w_v);           // 2
    gemm_mma<<<dim3(DIM/128, MROWS/128, 3), 256, GEMM_SMEM>>>(b_q, b_k, b_v, nullptr, 0); // 3
    split_wo<<<DIM, 256>>>(w_o);                                 // 4
    attn_mma<<<dim3(SEQ/128, BATCH*NH), 256, ATTN_SMEM>>>();     // 5
    gemm_mma<<<dim3(DIM/128, MROWS/128, 1), 256, GEMM_SMEM>>>(b_o, nullptr, nullptr, out, 1); // 6
}

// round 17
// speedup vs baseline: 1.3421x; 1.2510x over previous
#include <cuda_runtime.h>
#include <cuda_fp16.h>
#include <math.h>
#include <stdint.h>

#define BATCH 4
#define SEQ   2048
#define DIM   1024
#define NH    16
#define HD    64
#define MROWS (BATCH*SEQ)
#define ASZ   ((size_t)MROWS*2048)

// ---------------------------------------------------------------------------
// Scratch (__device__ globals; allocation-free rule)
// ---------------------------------------------------------------------------
// g_A3: per-z A operands. QKV inputs: fp16 hi-only, row width 1024 (first
// half of each buffer). Buffer 0 is later overwritten by attention ctx in
// [hi|lo] row-width-2048 layout for the o-projection.
__device__ __half g_A3[3*ASZ];
__device__ __half g_B2[(size_t)3*DIM*DIM];
__device__ __half g_B2o[(size_t)DIM*DIM];
// attention planes: Q fp16 (single), K/V fp16 hi/lo
__device__ __half g_Qh[BATCH*NH*SEQ*HD];
__device__ __half g_Kh[BATCH*NH*SEQ*HD];
__device__ __half g_Kl[BATCH*NH*SEQ*HD];
__device__ __half g_Vh[BATCH*NH*SEQ*HD];
__device__ __half g_Vl[BATCH*NH*SEQ*HD];
// RoPE tables
__device__ float g_costab[SEQ*32];
__device__ float g_sintab[SEQ*32];

__device__ __forceinline__ uint32_t smem_u32(const void* p) {
    uint32_t a;
    asm("{ .reg .u64 t; cvta.to.shared.u64 t, %1; cvt.u32.u64 %0, t; }" : "=r"(a) : "l"(p));
    return a;
}

#define LDMATRIX_X4(r0, r1, r2, r3, addr) \
    asm volatile("ldmatrix.sync.aligned.m8n8.x4.shared.b16 {%0,%1,%2,%3}, [%4];" \
        : "=r"(r0), "=r"(r1), "=r"(r2), "=r"(r3) : "r"(addr))

#define LDMATRIX_X4T(r0, r1, r2, r3, addr) \
    asm volatile("ldmatrix.sync.aligned.m8n8.x4.trans.shared.b16 {%0,%1,%2,%3}, [%4];" \
        : "=r"(r0), "=r"(r1), "=r"(r2), "=r"(r3) : "r"(addr))

#define MMA_F16(c, a, b0v, b1v) \
    asm volatile("mma.sync.aligned.m16n8k16.row.col.f32.f16.f16.f32 " \
        "{%0,%1,%2,%3}, {%4,%5,%6,%7}, {%8,%9}, {%0,%1,%2,%3};" \
        : "+f"((c)[0]), "+f"((c)[1]), "+f"((c)[2]), "+f"((c)[3]) \
        : "r"((a)[0]), "r"((a)[1]), "r"((a)[2]), "r"((a)[3]), "r"(b0v), "r"(b1v))

#define CP_ASYNC16(dst, src) \
    asm volatile("cp.async.cg.shared.global [%0], [%1], 16;" :: "r"(dst), "l"(src))
#define CP_COMMIT() asm volatile("cp.async.commit_group;" ::: "memory")
#define CP_WAIT0()  asm volatile("cp.async.wait_group 0;" ::: "memory")
#define CP_WAIT1()  asm volatile("cp.async.wait_group 1;" ::: "memory")

__device__ __forceinline__ uint32_t h2u(__half2 h) { return *reinterpret_cast<uint32_t*>(&h); }
__device__ __forceinline__ float ex2f(float x) {
    float y; asm("ex2.approx.f32 %0, %1;" : "=f"(y) : "f"(x)); return y;
}

struct h4 { __half2 a, b; };

#define QSCALE 0.18033688011112042f   // 0.125 * log2(e)

// ---------------------------------------------------------------------------
// RoPE table init
// ---------------------------------------------------------------------------
__global__ void init_tbl()
{
    int idx = blockIdx.x * blockDim.x + threadIdx.x;
    if (idx >= SEQ * 32) return;
    int lane = idx & 31;
    int s    = idx >> 5;
    float invf = (float)pow(10000.0, -(double)lane / 32.0);
    float sn, cs;
    sincosf((float)s * invf, &sn, &cs);
    g_costab[idx] = cs;
    g_sintab[idx] = sn;
}

// ---------------------------------------------------------------------------
// X convert x3: f32 -> fp16 (hi only), row width 1024, into g_A3[z]
// ---------------------------------------------------------------------------
__global__ void split_x3(const float* __restrict__ q, const float* __restrict__ k,
                         const float* __restrict__ v)
{
    int z = blockIdx.z;
    const float* src = (z == 0) ? q : (z == 1) ? k : v;
    int i = blockIdx.x * blockDim.x + threadIdx.x;
    if (i >= MROWS * 256) return;
    float4 vv = ((const float4*)src)[i];
    h4 hv;
    hv.a = __floats2half2_rn(vv.x, vv.y);
    hv.b = __floats2half2_rn(vv.z, vv.w);
    *(h4*)(g_A3 + (size_t)z * ASZ + (size_t)i * 4) = hv;
}

// ---------------------------------------------------------------------------
// W converts
// ---------------------------------------------------------------------------
__global__ void split_w3(const float* __restrict__ wq, const float* __restrict__ wk,
                         const float* __restrict__ wv)
{
    int z = blockIdx.z;
    const float* src = (z == 0) ? wq : (z == 1) ? wk : wv;
    int i = blockIdx.x * blockDim.x + threadIdx.x;
    if (i >= DIM * 256) return;
    float4 v = ((const float4*)src)[i];
    h4 hv;
    hv.a = __floats2half2_rn(v.x, v.y);
    hv.b = __floats2half2_rn(v.z, v.w);
    *(h4*)(g_B2 + (size_t)z * DIM * DIM + (size_t)i * 4) = hv;
}

__global__ void split_wo(const float* __restrict__ in)
{
    int i = blockIdx.x * blockDim.x + threadIdx.x;
    if (i >= DIM * 256) return;
    float4 v = ((const float4*)in)[i];
    h4 hv;
    hv.a = __floats2half2_rn(v.x, v.y);
    hv.b = __floats2half2_rn(v.z, v.w);
    *(h4*)(g_B2o + (size_t)i * 4) = hv;
}

// ---------------------------------------------------------------------------
// mma.sync fp16 GEMM, 3-stage pipeline, fused-QKV + RoPE epilogue.
// opro=0 (z=0..2): K'=1024 (X hi-only, stride 1024), RoPE epilogue,
//   z==0 Q single plane, z==1/2 hi/lo planes.
// opro=1: K'=2048 (ctx hi/lo, stride 2048), f32 dst.
// ---------------------------------------------------------------------------
#define STAGE_B  (128*144)
#define GEMM_SMEM (6*STAGE_B)            // 110592
#define EPF      136

__global__ __launch_bounds__(256)
void gemm_mma(const float* __restrict__ b0, const float* __restrict__ b1,
              const float* __restrict__ b2, float* __restrict__ dst_param,
              int opro)
{
    extern __shared__ __align__(16) char sm[];
    uint32_t sb = smem_u32(sm);

    int z = blockIdx.z;
    const float* bias = opro ? b0 : (z == 0) ? b0 : (z == 1) ? b1 : b2;
    const __half* Amat = g_A3 + (opro ? 0 : (size_t)z * ASZ);
    const __half* Bmat = opro ? g_B2o : g_B2 + (size_t)z * DIM * DIM;
    const int astride = opro ? 2048 : 1024;
    const int nst     = opro ? 32 : 16;

    int tid  = threadIdx.x;
    int lane = tid & 31;
    int wid  = tid >> 5;
    int wm   = wid & 1;
    int wn   = wid >> 1;
    int m0 = blockIdx.y << 7, n0 = blockIdx.x << 7;

    int lr = ((lane >> 3) & 1) * 8 + (lane & 7);
    int lk = (lane >> 4) * 8;

    float c[4][4][4];
    #pragma unroll
    for (int mf = 0; mf < 4; mf++)
        #pragma unroll
        for (int nf = 0; nf < 4; nf++)
            #pragma unroll
            for (int v = 0; v < 4; v++) c[mf][nf][v] = 0.0f;

    auto load_stage = [&](int t, int buf) {
        int kp = t << 6;
        int bc = kp & 1023;
        const __half* Ab = Amat + (size_t)m0 * astride + kp;
        const __half* Bb = Bmat + (size_t)n0 * 1024 + bc;
        uint32_t sa  = sb + buf * STAGE_B;
        uint32_t sbb = sb + 3 * STAGE_B + buf * STAGE_B;
        #pragma unroll
        for (int it = 0; it < 4; it++) {
            int id = tid + (it << 8);
            int r = id >> 3, ch = id & 7;
            CP_ASYNC16(sa  + r * 144 + (ch << 4), Ab + (size_t)r * astride + (ch << 3));
            CP_ASYNC16(sbb + r * 144 + (ch << 4), Bb + (size_t)r * 1024 + (ch << 3));
        }
        CP_COMMIT();
    };

    load_stage(0, 0);
    load_stage(1, 1);

    #pragma unroll 1
    for (int t = 0; t < nst; t++) {
        if (t + 1 < nst) { CP_WAIT1(); } else { CP_WAIT0(); }
        __syncthreads();
        if (t + 2 < nst) load_stage(t + 2, (t + 2) % 3);

        int buf = t % 3;
        uint32_t sa  = sb + buf * STAGE_B;
        uint32_t sbb = sb + 3 * STAGE_B + buf * STAGE_B;

        #pragma unroll
        for (int kk = 0; kk < 64; kk += 16) {
            uint32_t a[4][4];
            #pragma unroll
            for (int mf = 0; mf < 4; mf++) {
                uint32_t ad = sa + (uint32_t)(wm * 64 + mf * 16 + lr) * 144 + (kk + lk) * 2;
                LDMATRIX_X4(a[mf][0], a[mf][1], a[mf][2], a[mf][3], ad);
            }
            uint32_t b[2][4];
            #pragma unroll
            for (int nb = 0; nb < 2; nb++) {
                uint32_t bd = sbb + (uint32_t)(wn * 32 + nb * 16 + lr) * 144 + (kk + lk) * 2;
                LDMATRIX_X4(b[nb][0], b[nb][1], b[nb][2], b[nb][3], bd);
            }
            #pragma unroll
            for (int mf = 0; mf < 4; mf++) {
                #pragma unroll
                for (int nf = 0; nf < 4; nf++) {
                    int nb = nf >> 1;
                    uint32_t bb0 = (nf & 1) ? b[nb][1] : b[nb][0];
                    uint32_t bb1 = (nf & 1) ? b[nb][3] : b[nb][2];
                    MMA_F16(c[mf][nf], a[mf], bb0, bb1);
                }
            }
        }
        __syncthreads();
    }

    int rq = lane >> 2, cq = (lane & 3) * 2;
    float2 bv[4];
    #pragma unroll
    for (int nf = 0; nf < 4; nf++) {
        int col = n0 + wn * 32 + nf * 8 + cq;
        bv[nf] = make_float2(bias[col], bias[col + 1]);
    }

    if (opro) {
        #pragma unroll
        for (int mf = 0; mf < 4; mf++) {
            #pragma unroll
            for (int nf = 0; nf < 4; nf++) {
                int r   = m0 + wm * 64 + mf * 16 + rq;
                int col = n0 + wn * 32 + nf * 8 + cq;
                float2 lo = make_float2(c[mf][nf][0] + bv[nf].x, c[mf][nf][1] + bv[nf].y);
                float2 hi = make_float2(c[mf][nf][2] + bv[nf].x, c[mf][nf][3] + bv[nf].y);
                *(float2*)(dst_param + (size_t)r * 1024 + col)       = lo;
                *(float2*)(dst_param + (size_t)(r + 8) * 1024 + col) = hi;
            }
        }
        return;
    }

    // ---- fused RoPE + fp16 epilogue (z=0: Q single plane; z=1/2: hi/lo) ----
    float* st = (float*)sm;
    #pragma unroll
    for (int mf = 0; mf < 4; mf++) {
        #pragma unroll
        for (int nf = 0; nf < 4; nf++) {
            int r   = wm * 64 + mf * 16 + rq;
            int col = wn * 32 + nf * 8 + cq;
            *(float2*)&st[r * EPF + col] =
                make_float2(c[mf][nf][0] + bv[nf].x, c[mf][nf][1] + bv[nf].y);
            *(float2*)&st[(r + 8) * EPF + col] =
                make_float2(c[mf][nf][2] + bv[nf].x, c[mf][nf][3] + bv[nf].y);
        }
    }
    __syncthreads();

    int row = tid >> 1;
    int hsel = tid & 1;
    int m = m0 + row;
    int b = m >> 11, s = m & 2047;
    int h = (n0 >> 6) + hsel;

    float x[64];
    const float* xr = st + row * EPF + hsel * 64;
    #pragma unroll
    for (int i = 0; i < 16; i++)
        *(float4*)&x[i * 4] = *(const float4*)&xr[i * 4];

    __half* dh = (z == 0) ? g_Qh : (z == 1) ? g_Kh : g_Vh;
    __half* dl = (z == 1) ? g_Kl : g_Vl;     // unused for z==0
    size_t off = ((size_t)(b * NH + h) * SEQ + s) << 6;

    #pragma unroll
    for (int g = 0; g < 4; g++) {
        float v0[8], v1[8];
        if (z < 2) {
            #pragma unroll
            for (int j = 0; j < 8; j++) {
                int d = g * 8 + j;
                float cs = g_costab[(s << 5) + d];
                float sn = g_sintab[(s << 5) + d];
                v0[j] = x[d]      * cs - x[2*d + 1] * sn;
                v1[j] = x[d + 32] * cs + x[2*d]     * sn;
                if (z == 0) { v0[j] *= QSCALE; v1[j] *= QSCALE; }
            }
        } else {
            #pragma unroll
            for (int j = 0; j < 8; j++) {
                int d = g * 8 + j;
                v0[j] = x[d];
                v1[j] = x[d + 32];
            }
        }
        uint4 h0v, h1v;
        uint32_t* h0p = (uint32_t*)&h0v;
        uint32_t* h1p = (uint32_t*)&h1v;
        if (z == 0) {
            #pragma unroll
            for (int p = 0; p < 4; p++) {
                h0p[p] = h2u(__floats2half2_rn(v0[2*p], v0[2*p+1]));
                h1p[p] = h2u(__floats2half2_rn(v1[2*p], v1[2*p+1]));
            }
            *(uint4*)(dh + off + g * 8)      = h0v;
            *(uint4*)(dh + off + 32 + g * 8) = h1v;
        } else {
            uint4 l0v, l1v;
            uint32_t* l0p = (uint32_t*)&l0v;
            uint32_t* l1p = (uint32_t*)&l1v;
            #pragma unroll
            for (int p = 0; p < 4; p++) {
                __half2 hh0 = __floats2half2_rn(v0[2*p], v0[2*p+1]);
                __half2 ll0 = __floats2half2_rn(v0[2*p]   - __half2float(__low2half(hh0)),
                                                v0[2*p+1] - __half2float(__high2half(hh0)));
                h0p[p] = h2u(hh0); l0p[p] = h2u(ll0);
                __half2 hh1 = __floats2half2_rn(v1[2*p], v1[2*p+1]);
                __half2 ll1 = __floats2half2_rn(v1[2*p]   - __half2float(__low2half(hh1)),
                                                v1[2*p+1] - __half2float(__high2half(hh1)));
                h1p[p] = h2u(hh1); l1p[p] = h2u(ll1);
            }
            *(uint4*)(dh + off + g * 8)      = h0v;
            *(uint4*)(dh + off + 32 + g * 8) = h1v;
            *(uint4*)(dl + off + g * 8)      = l0v;
            *(uint4*)(dl + off + 32 + g * 8) = l1v;
        }
    }
}

// ---------------------------------------------------------------------------
// Flash attention: BM=128 (8 warps), BN=64, Q fp16 single plane in SMEM,
// K/V hi/lo double-buffered, f32 ex2 softmax, ones-MMA sums.
// S = q·kh + q·kl. SMEM: Q 18432 | KV stage0 36864 | KV stage1 36864 = 92160.
// ---------------------------------------------------------------------------
#define ROWB 144
#define QSM  18432
#define PLANE (64*ROWB)
#define KVST (4*PLANE)
#define ATTN_SMEM (QSM + 2*KVST)   // 92160

__global__ __launch_bounds__(256, 2)
void attn_mma()
{
    extern __shared__ __align__(16) char smb[];
    uint32_t sb = smem_u32(smb);

    int tid  = threadIdx.x;
    int lane = tid & 31;
    int wid  = tid >> 5;
    int bh   = blockIdx.y;
    int bx   = gridDim.x - 1 - blockIdx.x;
    int q0   = bx << 7;
    int nt   = 2 * bx + 2;

    const __half* Kh = g_Kh + (size_t)bh * SEQ * HD;
    const __half* Kl = g_Kl + (size_t)bh * SEQ * HD;
    const __half* Vh = g_Vh + (size_t)bh * SEQ * HD;
    const __half* Vl = g_Vl + (size_t)bh * SEQ * HD;

    int lr = ((lane >> 3) & 1) * 8 + (lane & 7);
    int lk = (lane >> 4) * 8;
    int rq = lane >> 2, cq = (lane & 3) * 2;

    auto load_kv = [&](int t, int stage) {
        int k0 = t << 6;
        uint32_t base = sb + QSM + stage * KVST;
        #pragma unroll
        for (int it = 0; it < 2; it++) {
            int id = tid + (it << 8);
            int r = id >> 3, ch = id & 7;
            uint32_t o = r * ROWB + (ch << 4);
            int go = ((k0 + r) << 6) + (ch << 3);
            CP_ASYNC16(base + o,             Kh + go);
            CP_ASYNC16(base + PLANE + o,     Kl + go);
            CP_ASYNC16(base + 2*PLANE + o,   Vh + go);
            CP_ASYNC16(base + 3*PLANE + o,   Vl + go);
        }
        CP_COMMIT();
    };

    // prologue: Q fp16 single plane
    {
        const __half* Qh = g_Qh + (size_t)bh * SEQ * HD;
        #pragma unroll
        for (int it = 0; it < 4; it++) {
            int id = tid + (it << 8);
            int r = id >> 3, ch = id & 7;
            CP_ASYNC16(sb + r * ROWB + (ch << 4), Qh + ((q0 + r) << 6) + (ch << 3));
        }
        CP_COMMIT();
    }
    load_kv(0, 0);

    float acc[8][4];
    #pragma unroll
    for (int nf = 0; nf < 8; nf++)
        #pragma unroll
        for (int v = 0; v < 4; v++) acc[nf][v] = 0.0f;
    float lacc[4] = {0.0f, 0.0f, 0.0f, 0.0f};
    float m_i[2] = {-1e30f, -1e30f};

    int wminrow = q0 + wid*16;

    CP_WAIT0();
    __syncthreads();

    #pragma unroll 1
    for (int t = 0; t < nt; t++) {
        int k0 = t << 6;
        if (t + 1 < nt) { load_kv(t + 1, (t + 1) & 1); CP_WAIT1(); }
        __syncthreads();

        uint32_t khb = sb + QSM + (t & 1) * KVST;
        uint32_t klb = khb + PLANE;
        uint32_t vhb = khb + 2*PLANE;
        uint32_t vlb = khb + 3*PLANE;

        // ---- S = q·kh + q·kl ----
        float sc[8][4];
        #pragma unroll
        for (int nf = 0; nf < 8; nf++)
            #pragma unroll
            for (int v = 0; v < 4; v++) sc[nf][v] = 0.0f;

        #pragma unroll
        for (int kc = 0; kc < 4; kc++) {
            uint32_t qoff = (uint32_t)(wid*16 + lr) * ROWB + (kc*16 + lk) * 2;
            uint32_t qh[4];
            LDMATRIX_X4(qh[0], qh[1], qh[2], qh[3], sb + qoff);
            #pragma unroll
            for (int nb = 0; nb < 4; nb++) {
                uint32_t off = (uint32_t)(nb*16 + lr) * ROWB + (kc*16 + lk) * 2;
                uint32_t bh0, bh1, bh2, bh3, bl0, bl1, bl2, bl3;
                LDMATRIX_X4(bh0, bh1, bh2, bh3, khb + off);
                LDMATRIX_X4(bl0, bl1, bl2, bl3, klb + off);
                MMA_F16(sc[2*nb],   qh, bh0, bh2);
                MMA_F16(sc[2*nb],   qh, bl0, bl2);
                MMA_F16(sc[2*nb+1], qh, bh1, bh3);
                MMA_F16(sc[2*nb+1], qh, bl1, bl3);
            }
        }

        if (k0 + 63 > wminrow) {
            int row0 = wminrow + rq;
            #pragma unroll
            for (int nf = 0; nf < 8; nf++) {
                int col = k0 + nf*8 + cq;
                if (col     > row0)     sc[nf][0] = -1e30f;
                if (col + 1 > row0)     sc[nf][1] = -1e30f;
                if (col     > row0 + 8) sc[nf][2] = -1e30f;
                if (col + 1 > row0 + 8) sc[nf][3] = -1e30f;
            }
        }

        uint32_t pr[8][2];
        #pragma unroll
        for (int i = 0; i < 2; i++) {
            float mx = -1e30f;
            #pragma unroll
            for (int nf = 0; nf < 8; nf++)
                mx = fmaxf(mx, fmaxf(sc[nf][2*i], sc[nf][2*i+1]));
            mx = fmaxf(mx, __shfl_xor_sync(0xffffffffu, mx, 1));
            mx = fmaxf(mx, __shfl_xor_sync(0xffffffffu, mx, 2));
            float mnew  = fmaxf(m_i[i], mx);
            float scale = ex2f(m_i[i] - mnew);
            float neg   = -mnew;
            #pragma unroll
            for (int nf = 0; nf < 8; nf++) {
                float p0 = ex2f(sc[nf][2*i]   + neg);
                float p1 = ex2f(sc[nf][2*i+1] + neg);
                asm("cvt.rn.f16x2.f32 %0, %1, %2;" : "=r"(pr[nf][i]) : "f"(p1), "f"(p0));
            }
            m_i[i] = mnew;
            lacc[2*i]   *= scale;
            lacc[2*i+1] *= scale;
            #pragma unroll
            for (int nf = 0; nf < 8; nf++) {
                acc[nf][2*i]   *= scale;
                acc[nf][2*i+1] *= scale;
            }
        }

        #pragma unroll
        for (int kc = 0; kc < 4; kc++) {
            uint32_t ph[4] = { pr[2*kc][0], pr[2*kc][1], pr[2*kc+1][0], pr[2*kc+1][1] };
            MMA_F16(lacc, ph, 0x3C003C00u, 0x3C003C00u);
            #pragma unroll
            for (int db = 0; db < 4; db++) {
                uint32_t off = (uint32_t)(kc*16 + (lane & 15)) * ROWB
                             + (db*16 + ((lane >> 4) << 3)) * 2;
                uint32_t vh0, vh1, vh2, vh3, vl0, vl1, vl2, vl3;
                LDMATRIX_X4T(vh0, vh1, vh2, vh3, vhb + off);
                LDMATRIX_X4T(vl0, vl1, vl2, vl3, vlb + off);
                MMA_F16(acc[2*db],   ph, vh0, vh1);
                MMA_F16(acc[2*db],   ph, vl0, vl1);
                MMA_F16(acc[2*db+1], ph, vh2, vh3);
                MMA_F16(acc[2*db+1], ph, vl2, vl3);
            }
        }
        __syncthreads();
    }

    // epilogue: normalize + fp16 hi/lo split into g_A3[0] (row width 2048)
    int b = bh >> 4, h = bh & 15;
    #pragma unroll
    for (int i = 0; i < 2; i++) {
        float inv = 1.0f / lacc[2*i];
        int s = q0 + wid*16 + rq + 8*i;
        __half* rowp = g_A3 + ((size_t)(b * SEQ + s) << 11) + (h << 6);
        #pragma unroll
        for (int nf = 0; nf < 8; nf++) {
            float v0 = acc[nf][2*i]   * inv;
            float v1 = acc[nf][2*i+1] * inv;
            __half2 hv = __floats2half2_rn(v0, v1);
            __half2 lv = __floats2half2_rn(v0 - __half2float(__low2half(hv)),
                                           v1 - __half2float(__high2half(hv)));
            *(__half2*)(rowp + nf*8 + cq)        = hv;
            *(__half2*)(rowp + 1024 + nf*8 + cq) = lv;
        }
    }
}

// ---------------------------------------------------------------------------
extern "C" void kernel_launch(void* const* d_in, const int* in_sizes, int n_in,
                              void* d_out, int out_size)
{
    const float* query = (const float*)d_in[0];
    const float* key   = (const float*)d_in[1];
    const float* value = (const float*)d_in[2];
    const float* w_q = (const float*)d_in[4];
    const float* b_q = (const float*)d_in[5];
    const float* w_k = (const float*)d_in[6];
    const float* b_k = (const float*)d_in[7];
    const float* w_v = (const float*)d_in[8];
    const float* b_v = (const float*)d_in[9];
    const float* w_o = (const float*)d_in[10];
    const float* b_o = (const float*)d_in[11];
    float* out = (float*)d_out;

    static int attr_set = 0;
    if (!attr_set) {
        cudaFuncSetAttribute(gemm_mma, cudaFuncAttributeMaxDynamicSharedMemorySize, GEMM_SMEM);
        cudaFuncSetAttribute(attn_mma, cudaFuncAttributeMaxDynamicSharedMemorySize, ATTN_SMEM);
        attr_set = 1;
    }

    init_tbl<<<SEQ*32/256, 256>>>();                             // 0
    split_x3<<<dim3(MROWS, 1, 3), 256>>>(query, key, value);     // 1
    split_w3<<<dim3(DIM, 1, 3), 256>>>(w_q, w_k, w_v);           // 2
    gemm_mma<<<dim3(DIM/128, MROWS/128, 3), 256, GEMM_SMEM>>>(b_q, b_k, b_v, nullptr, 0); // 3
    split_wo<<<DIM, 256>>>(w_o);                                 // 4
    attn_mma<<<dim3(SEQ/128, BATCH*NH), 256, ATTN_SMEM>>>();     // 5
    gemm_mma<<<dim3(DIM/128, MROWS/128, 1), 256, GEMM_SMEM>>>(b_o, nullptr, nullptr, out, 1); // 6
}